// round 14
// baseline (speedup 1.0000x reference)
#include <cuda_runtime.h>

// DRNN: two stacked SimpleRNN(tanh), round 11. B=512, T=512, D=64, H=100.
//
// Kernel 1 (xp_prepass v4): XP[b,t,u] = x_{b,t}.W1x[:,u] + b1[u]  — a pure
//   [262144,64]@[64,100] GEMM, register-tiled 4t x 5u per thread:
//   each k-quad iter does 9 LDS.128 -> 40 FFMA2 (1:4.4) with 20 independent
//   f32x2 accumulator chains. x-tile rows padded to 68 floats (272B stride,
//   gcd(17,32)=1 -> conflict-free across the 16 per-phase t addresses);
//   W transposed [u][k] in smem -> weight loads are warp-broadcast.
//   320 thr = 16 t-blocks x 20 u-blocks (64t x 100u exact), grid (8, 512),
//   ~100 regs, 2 CTAs/SM.
//
// Kernel 2 (mainloop): UNCHANGED from round 10 (proven 627us): 128 CTAs x
//   4 rows, 256 thr, all warps 2 units/lane (100 u64 wregs), 600 LDS/step,
//   per-SMSP exactly 600 FFMA2 (balanced 1200-cyc floor):
//   G1 (wid 0-3) row-split 2 rows/warp; G2a (wid 4,5); G2b (wid 6,7).
//   Pairwise named barriers bar2 (G1+G2a), bar3 (G2a+G2b).

#define TT   512
#define BB   512
#define DD   64
#define HH   100
#define ROWS 4
#define HSR  104    // h/p row stride
#define NTHR 256
#define XPAD 68     // prepass x-tile row stride (272B: conflict-free)

#define BAR_SYNC(id, cnt) asm volatile("bar.sync %0, %1;" :: "r"(id), "r"(cnt) : "memory")

__device__ float XPbuf[(size_t)BB * TT * HH];   // 104.8 MB scratch

__device__ __forceinline__ void ffma2(unsigned long long &acc,
                                      unsigned long long a,
                                      unsigned long long b) {
    asm("fma.rn.f32x2 %0, %1, %2, %0;" : "+l"(acc) : "l"(a), "l"(b));
}

__device__ __forceinline__ unsigned long long pack2(float lo, float hi) {
    unsigned long long r;
    asm("mov.b64 %0, {%1, %2};" : "=l"(r) : "f"(lo), "f"(hi));
    return r;
}

__device__ __forceinline__ float hsum2(unsigned long long v) {
    float lo, hi;
    asm("mov.b64 {%0, %1}, %2;" : "=f"(lo), "=f"(hi) : "l"(v));
    return lo + hi;
}

__device__ __forceinline__ ulonglong2 lds128(const float* p) {
    return *reinterpret_cast<const ulonglong2*>(p);
}

// tanh via exp + fast divide: ~1e-7 rel err.
__device__ __forceinline__ float tanh_f(float x) {
    float ax = fabsf(x);
    float e  = __expf(-2.0f * ax);
    float r  = __fdividef(1.0f - e, 1.0f + e);
    return copysignf(r, x);
}

// ───────────────────────── Kernel 1: XP pre-pass v4 (GEMM-tiled) ─────────
// grid (8, 512): blockIdx.x = 64-timestep tile, blockIdx.y = batch row.
// 320 thr: tb = tid&15 -> 4 timesteps (tb*4..+3); ub = tid>>4 -> 5 units.
__global__ __launch_bounds__(320, 2)
void xp_prepass(const float* __restrict__ X, const float* __restrict__ W1x,
                const float* __restrict__ B1)
{
    __shared__ __align__(16) float sW [HH][DD];    // W1x transposed [u][k]
    __shared__ __align__(16) float sXT[64][XPAD];  // x tile, padded rows

    const int b   = blockIdx.y;
    const int t0  = blockIdx.x * 64;
    const int tid = threadIdx.x;
    const int tb  = tid & 15;
    const int ub  = tid >> 4;                      // 0..19
    const int u_base = ub * 5;                     // 0,5,...,95

    // Load W transposed: 6400 floats, 20 per thread.
    for (int idx = tid; idx < HH * DD; idx += 320) {
        int u = idx >> 6, k = idx & 63;
        sW[u][k] = W1x[k * HH + u];
    }
    // Load x tile: 64 t x 64 k (contiguous in gmem), float4, padded store.
    for (int idx = tid; idx < 64 * 16; idx += 320) {
        int t = idx >> 4, q = idx & 15;
        float4 v = reinterpret_cast<const float4*>(
            X + ((size_t)b * TT + t0) * DD)[idx];
        *reinterpret_cast<float4*>(&sXT[t][q * 4]) = v;
    }
    __syncthreads();

    unsigned long long acc[4][5];
    #pragma unroll
    for (int i = 0; i < 4; ++i)
        #pragma unroll
        for (int j = 0; j < 5; ++j) acc[i][j] = 0ull;

    #pragma unroll
    for (int kq = 0; kq < 16; ++kq) {
        ulonglong2 xv[4];
        #pragma unroll
        for (int i = 0; i < 4; ++i)
            xv[i] = lds128(&sXT[tb * 4 + i][kq * 4]);
        ulonglong2 wv[5];
        #pragma unroll
        for (int j = 0; j < 5; ++j)
            wv[j] = lds128(&sW[u_base + j][kq * 4]);
        #pragma unroll
        for (int i = 0; i < 4; ++i) {
            #pragma unroll
            for (int j = 0; j < 5; ++j) {
                ffma2(acc[i][j], xv[i].x, wv[j].x);
                ffma2(acc[i][j], xv[i].y, wv[j].y);
            }
        }
    }

    float bj[5];
    #pragma unroll
    for (int j = 0; j < 5; ++j) bj[j] = B1[u_base + j];

    #pragma unroll
    for (int i = 0; i < 4; ++i) {
        float* dst = &XPbuf[((size_t)b * TT + t0 + tb * 4 + i) * HH + u_base];
        #pragma unroll
        for (int j = 0; j < 5; ++j)
            dst[j] = hsum2(acc[i][j]) + bj[j];
    }
}

// ───────────────────────── Kernel 2: main recurrence (unchanged) ─────────

// G2 accumulate: 4 rows x 2 units. acc[r]=unit0, acc[4+r]=unit1.
__device__ __forceinline__ void accum8_h(unsigned long long (&acc)[8],
                                         const float* base,
                                         const unsigned long long* w)
{
    #pragma unroll
    for (int it = 0; it < 25; ++it) {
        ulonglong2 v0 = lds128(base + 0*HSR + 4*it);
        ulonglong2 v1 = lds128(base + 1*HSR + 4*it);
        ulonglong2 v2 = lds128(base + 2*HSR + 4*it);
        ulonglong2 v3 = lds128(base + 3*HSR + 4*it);
        unsigned long long wA0 = w[4*it + 0];
        unsigned long long wB0 = w[4*it + 1];
        unsigned long long wA1 = w[4*it + 2];
        unsigned long long wB1 = w[4*it + 3];
        ffma2(acc[0], v0.x, wA0); ffma2(acc[4], v0.x, wA1);
        ffma2(acc[1], v1.x, wA0); ffma2(acc[5], v1.x, wA1);
        ffma2(acc[2], v2.x, wA0); ffma2(acc[6], v2.x, wA1);
        ffma2(acc[3], v3.x, wA0); ffma2(acc[7], v3.x, wA1);
        ffma2(acc[0], v0.y, wB0); ffma2(acc[4], v0.y, wB1);
        ffma2(acc[1], v1.y, wB0); ffma2(acc[5], v1.y, wB1);
        ffma2(acc[2], v2.y, wB0); ffma2(acc[6], v2.y, wB1);
        ffma2(acc[3], v3.y, wB0); ffma2(acc[7], v3.y, wB1);
    }
}

// G1 accumulate: 2 rows x 2 units. acc = {r0u0, r1u0, r0u1, r1u1}.
__device__ __forceinline__ void accum4_g1(unsigned long long (&acc)[4],
                                          const float* base,
                                          const unsigned long long* w)
{
    #pragma unroll
    for (int it = 0; it < 25; ++it) {
        ulonglong2 v0 = lds128(base + 0*HSR + 4*it);
        ulonglong2 v1 = lds128(base + 1*HSR + 4*it);
        unsigned long long wA0 = w[4*it + 0];
        unsigned long long wB0 = w[4*it + 1];
        unsigned long long wA1 = w[4*it + 2];
        unsigned long long wB1 = w[4*it + 3];
        ffma2(acc[0], v0.x, wA0); ffma2(acc[1], v1.x, wA0);
        ffma2(acc[2], v0.x, wA1); ffma2(acc[3], v1.x, wA1);
        ffma2(acc[0], v0.y, wB0); ffma2(acc[1], v1.y, wB0);
        ffma2(acc[2], v0.y, wB1); ffma2(acc[3], v1.y, wB1);
    }
}

__global__ __launch_bounds__(NTHR, 1)
void drnn_kernel(const float* __restrict__ W1h,
                 const float* __restrict__ W2x, const float* __restrict__ W2h,
                 const float* __restrict__ B2,
                 const float* __restrict__ Wo,  const float* __restrict__ Bo,
                 float* __restrict__ out)
{
    __shared__ __align__(16) float sH1[2][ROWS][HSR];
    __shared__ __align__(16) float sH2[2][ROWS][HSR];
    __shared__ __align__(16) float sP [2][ROWS][HSR];   // p = W2x.h1 + b2

    const int tid  = threadIdx.x;
    const int wid  = tid >> 5;
    const int lane = tid & 31;
    const int r0   = blockIdx.x * ROWS;
    const int gid  = (wid < 4) ? 0 : ((wid < 6) ? 1 : 2);
    const int uh   = wid & 1;
    const int u0r  = uh * 64 + 2 * lane;
    const bool act = (u0r < HH);
    const int u0   = act ? u0r : (HH - 2);
    const int rp   = (wid >> 1) & 1;

    unsigned long long w[100];
    float bj0 = 0.f, bj1 = 0.f;
    {
        const float* Wsrc = (gid == 0) ? W1h : ((gid == 1) ? W2x : W2h);
        #pragma unroll
        for (int q = 0; q < 25; ++q) {
            int k = 4 * q;
            w[4*q+0] = pack2(Wsrc[(k  )*HH + u0  ], Wsrc[(k+1)*HH + u0  ]);
            w[4*q+1] = pack2(Wsrc[(k+2)*HH + u0  ], Wsrc[(k+3)*HH + u0  ]);
            w[4*q+2] = pack2(Wsrc[(k  )*HH + u0+1], Wsrc[(k+1)*HH + u0+1]);
            w[4*q+3] = pack2(Wsrc[(k+2)*HH + u0+1], Wsrc[(k+3)*HH + u0+1]);
        }
        if (gid == 1) { bj0 = B2[u0]; bj1 = B2[u0 + 1]; }
    }

    {
        float* z1 = &sH1[0][0][0];
        for (int idx = tid; idx < 2*ROWS*HSR; idx += NTHR) z1[idx] = 0.f;
        float* z2 = &sH2[0][0][0];
        for (int idx = tid; idx < 2*ROWS*HSR; idx += NTHR) z2[idx] = 0.f;
    }
    __syncthreads();

    float2 xcur[2];
    if (gid == 0) {
        #pragma unroll
        for (int r = 0; r < 2; ++r)
            xcur[r] = *reinterpret_cast<const float2*>(
                &XPbuf[((size_t)(r0 + rp*2 + r) * TT + 0) * HH + u0]);
    }

    for (int i = 0; i <= TT + 1; ++i) {
        const int pc = i & 1, pn = pc ^ 1;
        if (gid == 0) {
            if (i <= TT - 1) {                           // h1_i (2 rows)
                float2 xn[2];
                const bool pf = (i + 1 <= TT - 1);
                if (pf) {
                    #pragma unroll
                    for (int r = 0; r < 2; ++r)
                        xn[r] = *reinterpret_cast<const float2*>(
                            &XPbuf[((size_t)(r0 + rp*2 + r) * TT + (i+1)) * HH + u0]);
                }
                unsigned long long a[4] = {0ull, 0ull, 0ull, 0ull};
                accum4_g1(a, &sH1[pn][rp*2][0], w);
                if (act) {
                    float2 o0, o1;
                    o0.x = tanh_f(hsum2(a[0]) + xcur[0].x);
                    o0.y = tanh_f(hsum2(a[2]) + xcur[0].y);
                    o1.x = tanh_f(hsum2(a[1]) + xcur[1].x);
                    o1.y = tanh_f(hsum2(a[3]) + xcur[1].y);
                    *reinterpret_cast<float2*>(&sH1[pc][rp*2    ][u0]) = o0;
                    *reinterpret_cast<float2*>(&sH1[pc][rp*2 + 1][u0]) = o1;
                }
                if (pf) { xcur[0] = xn[0]; xcur[1] = xn[1]; }
            }
            BAR_SYNC(2, 192);
        } else if (gid == 1) {
            if (i >= 1 && i <= TT) {                     // p_{i-1} (4 rows)
                unsigned long long a[8];
                #pragma unroll
                for (int n = 0; n < 8; ++n) a[n] = 0ull;
                accum8_h(a, &sH1[pn][0][0], w);
                if (act) {
                    #pragma unroll
                    for (int r = 0; r < ROWS; ++r) {
                        float2 v;
                        v.x = hsum2(a[r])   + bj0;
                        v.y = hsum2(a[4+r]) + bj1;
                        *reinterpret_cast<float2*>(&sP[pn][r][u0]) = v;
                    }
                }
            }
            BAR_SYNC(3, 128);
            BAR_SYNC(2, 192);
        } else {
            if (i >= 2) {                                // h2_{i-2} (4 rows)
                float2 pv[4];
                #pragma unroll
                for (int r = 0; r < ROWS; ++r)
                    pv[r] = *reinterpret_cast<const float2*>(&sP[pc][r][u0]);
                unsigned long long a[8];
                #pragma unroll
                for (int n = 0; n < 8; ++n) a[n] = 0ull;
                accum8_h(a, &sH2[pn][0][0], w);
                if (act) {
                    #pragma unroll
                    for (int r = 0; r < ROWS; ++r) {
                        float2 v;
                        v.x = tanh_f(hsum2(a[r])   + pv[r].x);
                        v.y = tanh_f(hsum2(a[4+r]) + pv[r].y);
                        *reinterpret_cast<float2*>(&sH2[pc][r][u0]) = v;
                    }
                }
            }
            BAR_SYNC(3, 128);
        }
    }
    __syncthreads();

    float* outVec = out;                      // [512]
    float* outH1  = out + BB;                 // [512,100]
    float* outH2  = out + BB + BB*HH;         // [512,100]

    for (int idx = tid; idx < ROWS*HH; idx += NTHR) {
        int r = idx / HH, uu = idx % HH;
        outH1[(size_t)(r0 + r)*HH + uu] = sH1[1][r][uu];
        outH2[(size_t)(r0 + r)*HH + uu] = sH2[1][r][uu];
    }

    if (tid < 32) {
        #pragma unroll
        for (int r = 0; r < ROWS; ++r) {
            float v = 0.f;
            #pragma unroll
            for (int mm = 0; mm < 4; ++mm) {
                int uu = mm*32 + tid;
                if (uu < HH) v += sH2[1][r][uu] * Wo[uu];
            }
            #pragma unroll
            for (int off = 16; off; off >>= 1)
                v += __shfl_down_sync(0xffffffffu, v, off);
            if (tid == 0) outVec[r0 + r] = v + Bo[0];
        }
    }
}

extern "C" void kernel_launch(void* const* d_in, const int* in_sizes, int n_in,
                              void* d_out, int out_size) {
    (void)in_sizes; (void)n_in; (void)out_size;
    const float* X   = (const float*)d_in[0];
    const float* W1x = (const float*)d_in[1];
    const float* W1h = (const float*)d_in[2];
    const float* B1  = (const float*)d_in[3];
    const float* W2x = (const float*)d_in[4];
    const float* W2h = (const float*)d_in[5];
    const float* B2  = (const float*)d_in[6];
    const float* Wo  = (const float*)d_in[7];
    const float* Bo  = (const float*)d_in[8];

    dim3 pgrid(8, BB);
    xp_prepass<<<pgrid, 320>>>(X, W1x, B1);
    drnn_kernel<<<BB/ROWS, NTHR>>>(W1h, W2x, W2h, B2, Wo, Bo, (float*)d_out);
}